// round 6
// baseline (speedup 1.0000x reference)
#include <cuda_runtime.h>
#include <cuda_bf16.h>
#include <cstdint>

#define B_   64
#define T_   4096
#define IN_  32
#define H_   128
#define G_   384
#define OUT_ 32
#define BT_  (B_ * T_)

// ---------------- scratch (static __device__; allocation-free rule) ----------
__device__ float g_gi[(size_t)BT_ * G_];   // gate pre-activations (reused L0 then L1)
__device__ float g_y0[(size_t)BT_ * H_];   // layer-0 outputs

typedef unsigned long long u64t;

// ---------------- packed f32x2 helpers (sm_103a FFMA2 via PTX) ---------------
__device__ __forceinline__ u64t pk2(float a, float b) {
    u64t r; asm("mov.b64 %0, {%1,%2};" : "=l"(r) : "f"(a), "f"(b)); return r;
}
__device__ __forceinline__ u64t fma2(u64t a, u64t b, u64t c) {
    u64t d; asm("fma.rn.f32x2 %0, %1, %2, %3;" : "=l"(d) : "l"(a), "l"(b), "l"(c)); return d;
}
__device__ __forceinline__ u64t add2(u64t a, u64t b) {
    u64t d; asm("add.rn.f32x2 %0, %1, %2;" : "=l"(d) : "l"(a), "l"(b)); return d;
}
__device__ __forceinline__ float2 upk2(u64t a) {
    float2 f; asm("mov.b64 {%0,%1}, %2;" : "=f"(f.x), "=f"(f.y) : "l"(a)); return f;
}

__device__ __forceinline__ float sigmf(float x) {
    return __fdividef(1.f, 1.f + __expf(-x));
}
__device__ __forceinline__ float tanhfast(float x) {
    float e = __expf(-2.f * x);
    return __fdividef(1.f - e, 1.f + e);
}

// ============================================================================
// K1: gi0 = x @ W_ih0^T + b_ih0    (x: [BT,32], W: [384,32]) -> g_gi [BT,384]
// ============================================================================
__global__ void k1_gi0(const float* __restrict__ x,
                       const float* __restrict__ W,
                       const float* __restrict__ b) {
    __shared__ __align__(16) float sx[16 * IN_];
    const int tid = threadIdx.x;                 // gate row 0..383
    const size_t bt0 = (size_t)blockIdx.x * 16;

    for (int i = tid; i < 16 * IN_; i += 384) sx[i] = x[bt0 * IN_ + i];

    u64t wp[16];
    {
        const float4* wr = (const float4*)(W + (size_t)tid * IN_);
#pragma unroll
        for (int q = 0; q < 8; q++) {
            float4 w4 = __ldg(wr + q);
            wp[2 * q]     = pk2(w4.x, w4.y);
            wp[2 * q + 1] = pk2(w4.z, w4.w);
        }
    }
    const float bias = __ldg(b + tid);
    __syncthreads();

#pragma unroll 4
    for (int row = 0; row < 16; row++) {
        const ulonglong2* xr = (const ulonglong2*)(sx + row * IN_);
        u64t a0 = 0ull, a1 = 0ull;
#pragma unroll
        for (int q = 0; q < 8; q++) {
            ulonglong2 xp = xr[q];
            a0 = fma2(wp[2 * q],     xp.x, a0);
            a1 = fma2(wp[2 * q + 1], xp.y, a1);
        }
        float2 s = upk2(add2(a0, a1));
        g_gi[(bt0 + row) * G_ + tid] = s.x + s.y + bias;
    }
}

// ============================================================================
// K3: gi1 = y0 @ W_ih1^T + b_ih1   (y0: [BT,128], W: [384,128]) -> g_gi
// ============================================================================
__global__ void k3_gi1(const float* __restrict__ W,
                       const float* __restrict__ b) {
    __shared__ float sA[16][64];
    __shared__ float sB[16][64];
    const int tid = threadIdx.x;
    const int m0 = blockIdx.x * 64;   // bt rows
    const int n0 = blockIdx.y * 64;   // gate rows
    const int tx = tid & 15, ty = tid >> 4;
    const int lrow = tid >> 2, lk = (tid & 3) * 4;

    u64t acc2[4][2] = {};
    for (int k0 = 0; k0 < H_; k0 += 16) {
        float4 a4 = *(const float4*)(g_y0 + (size_t)(m0 + lrow) * H_ + k0 + lk);
        float4 b4 = __ldg((const float4*)(W + (size_t)(n0 + lrow) * H_ + k0 + lk));
        sA[lk + 0][lrow] = a4.x; sA[lk + 1][lrow] = a4.y;
        sA[lk + 2][lrow] = a4.z; sA[lk + 3][lrow] = a4.w;
        sB[lk + 0][lrow] = b4.x; sB[lk + 1][lrow] = b4.y;
        sB[lk + 2][lrow] = b4.z; sB[lk + 3][lrow] = b4.w;
        __syncthreads();
#pragma unroll
        for (int kk = 0; kk < 16; kk++) {
            float4 av = *(const float4*)(&sA[kk][ty * 4]);
            float4 bv = *(const float4*)(&sB[kk][tx * 4]);
            u64t b01 = pk2(bv.x, bv.y), b23 = pk2(bv.z, bv.w);
            float aa[4] = {av.x, av.y, av.z, av.w};
#pragma unroll
            for (int i = 0; i < 4; i++) {
                u64t ai = pk2(aa[i], aa[i]);
                acc2[i][0] = fma2(ai, b01, acc2[i][0]);
                acc2[i][1] = fma2(ai, b23, acc2[i][1]);
            }
        }
        __syncthreads();
    }
    float4 bv = __ldg((const float4*)(b + n0 + tx * 4));
#pragma unroll
    for (int i = 0; i < 4; i++) {
        float2 p01 = upk2(acc2[i][0]), p23 = upk2(acc2[i][1]);
        float4 o;
        o.x = p01.x + bv.x; o.y = p01.y + bv.y;
        o.z = p23.x + bv.z; o.w = p23.y + bv.w;
        *(float4*)(g_gi + (size_t)(m0 + ty * 4 + i) * G_ + n0 + tx * 4) = o;
    }
}

// ============================================================================
// K2/K4: GRU recurrence — pair-split layout, ONE barrier per step.
// 64 CTAs (one per batch), 256 threads. Pair (2j, 2j+1) owns h-element j:
//   even lane: k in [0,64)  of rows r_j, z_j, n_j (register-resident)
//   odd  lane: k in [64,128) of the same rows
// Partials combine via shfl_xor(1). Even lane does r/n/h-update; odd lane
// does z and (layer 1) the FC head for step t-1 from padded SMEM blocks.
// ============================================================================
__global__ void __launch_bounds__(256, 1) k_scan(
    const float* __restrict__ Whh, const float* __restrict__ bhh,
    const int store_y, float* __restrict__ h_final,
    const float* __restrict__ fcw, const float* __restrict__ fcb,
    float* __restrict__ out, const int do_fc)
{
    __shared__ __align__(16) float sh0[H_];
    __shared__ __align__(16) float sh1[H_];
    __shared__ __align__(16) float sfcB[128 * 36];   // per-odd-lane FC weight blocks
    __shared__ float sfcb[OUT_];

    const int tid  = threadIdx.x;
    const int b    = blockIdx.x;
    const int j    = tid >> 1;          // h element 0..127
    const int odd  = tid & 1;
    const int kb   = odd * 64;          // my k-half
    const int lane = tid & 31;
    const int wrp  = tid >> 5;

    // ---- register-resident weight halves (3 rows x 64 cols) ----
    u64t wr[32], wz[32], wn[32];
    {
        const float4* pr = (const float4*)(Whh + (size_t)j * H_ + kb);
        const float4* pz = (const float4*)(Whh + (size_t)(128 + j) * H_ + kb);
        const float4* pn = (const float4*)(Whh + (size_t)(256 + j) * H_ + kb);
#pragma unroll
        for (int q = 0; q < 16; q++) {
            float4 a = __ldg(pr + q); wr[2*q] = pk2(a.x, a.y); wr[2*q+1] = pk2(a.z, a.w);
            float4 c = __ldg(pz + q); wz[2*q] = pk2(c.x, c.y); wz[2*q+1] = pk2(c.z, c.w);
            float4 d = __ldg(pn + q); wn[2*q] = pk2(d.x, d.y); wn[2*q+1] = pk2(d.z, d.w);
        }
    }
    float bias_A, bias_n = 0.f;                 // A: r (even) / z (odd)
    if (!odd) { bias_A = __ldg(bhh + j); bias_n = __ldg(bhh + 256 + j); }
    else      { bias_A = __ldg(bhh + 128 + j); }

    // FC block setup (odd lanes): output o, h-chunk m, conflict-padded block
    const int og = lane >> 3;                   // 0..3
    const int om = (lane >> 1) & 3;             // 0..3
    const int o  = wrp * 4 + og;
    const int blk = wrp * 16 + og * 4 + om;
    float* myblk = sfcB + blk * 36;

    if (tid < H_) sh0[tid] = 0.f;
    if (do_fc) {
        if (odd) {
            const float4* src = (const float4*)(fcw + (size_t)o * H_ + om * 32);
#pragma unroll
            for (int i = 0; i < 8; i++) ((float4*)myblk)[i] = __ldg(src + i);
        }
        if (tid < OUT_) sfcb[tid] = fcb[tid];
    }
    __syncthreads();

    const size_t gbase = (size_t)b * T_ * G_;
    const float* gA  = g_gi + gbase + (odd ? 128 + j : j);   // r or z stream
    const float* gN  = g_gi + gbase + 256 + j;               // n stream (even only)
    float gA_c = __ldg(gA);
    float gA_1 = __ldg(gA + G_);
    float gN_c = odd ? 0.f : __ldg(gN);
    float gN_1 = odd ? 0.f : __ldg(gN + G_);

    float* hcur = sh0;
    float* hnxt = sh1;
    float* ybase = g_y0 + (size_t)b * T_ * H_ + j;
    float* obase = out + (size_t)b * T_ * OUT_;

    for (int t = 0; t < T_; t++) {
        // distance-2 gi prefetch (hidden under the matvec)
        const int t2 = (t + 2 < T_) ? t + 2 : T_ - 1;
        const float gA_2 = __ldg(gA + (size_t)t2 * G_);
        const float gN_2 = odd ? 0.f : __ldg(gN + (size_t)t2 * G_);

        // ---- half-matvec for all three gates (96 fma2, uniform code) ----
        u64t ar0 = 0ull, ar1 = 0ull, az0 = 0ull, az1 = 0ull, an0 = 0ull, an1 = 0ull;
        const ulonglong2* h2 = (const ulonglong2*)(hcur + kb);
#pragma unroll
        for (int q = 0; q < 16; q++) {
            ulonglong2 hp = h2[q];
            ar0 = fma2(wr[2*q],   hp.x, ar0);
            ar1 = fma2(wr[2*q+1], hp.y, ar1);
            az0 = fma2(wz[2*q],   hp.x, az0);
            az1 = fma2(wz[2*q+1], hp.y, az1);
            an0 = fma2(wn[2*q],   hp.x, an0);
            an1 = fma2(wn[2*q+1], hp.y, an1);
        }
        float2 fr = upk2(add2(ar0, ar1));
        float2 fz = upk2(add2(az0, az1));
        float2 fn = upk2(add2(an0, an1));
        float pr = fr.x + fr.y, pz = fz.x + fz.y, pn = fn.x + fn.y;

        // combine halves across the lane pair
        pr += __shfl_xor_sync(0xffffffffu, pr, 1);
        pz += __shfl_xor_sync(0xffffffffu, pz, 1);
        pn += __shfl_xor_sync(0xffffffffu, pn, 1);

        // my primary gate: even -> r, odd -> z
        const float ghA = odd ? pz : pr;
        const float gate = sigmf(gA_c + ghA + bias_A);
        const float zval = __shfl_xor_sync(0xffffffffu, gate, 1);  // even receives z

        if (!odd) {
            const float nv = tanhfast(fmaf(gate, pn + bias_n, gN_c));
            const float hold = hcur[j];
            const float hnew = fmaf(zval, hold - nv, nv);          // (1-z)n + z h
            hnxt[j] = hnew;
            if (store_y) ybase[(size_t)t * H_] = hnew;
        } else if (do_fc && t > 0) {
            // FC for step t-1 on hcur (= h_{t-1}); 32 MACs + 8-lane-group reduce
            const ulonglong2* fw2 = (const ulonglong2*)myblk;
            const ulonglong2* hh2 = (const ulonglong2*)(hcur + om * 32);
            u64t f0 = 0ull, f1 = 0ull;
#pragma unroll
            for (int i = 0; i < 8; i++) {
                ulonglong2 a = fw2[i], h = hh2[i];
                f0 = fma2(a.x, h.x, f0);
                f1 = fma2(a.y, h.y, f1);
            }
            float2 ff = upk2(add2(f0, f1));
            float s = ff.x + ff.y;
            s += __shfl_xor_sync(0xAAAAAAAAu, s, 2);
            s += __shfl_xor_sync(0xAAAAAAAAu, s, 4);
            if ((lane & 7) == 1) obase[(size_t)(t - 1) * OUT_ + o] = s + sfcb[o];
        }
        __syncthreads();                                           // the one barrier

        float* tmp = hcur; hcur = hnxt; hnxt = tmp;
        gA_c = gA_1; gA_1 = gA_2;
        gN_c = gN_1; gN_1 = gN_2;
    }

    // final-step FC (h_{T-1} is in hcur after the last swap)
    if (do_fc && odd) {
        const ulonglong2* fw2 = (const ulonglong2*)myblk;
        const ulonglong2* hh2 = (const ulonglong2*)(hcur + om * 32);
        u64t f0 = 0ull, f1 = 0ull;
#pragma unroll
        for (int i = 0; i < 8; i++) {
            ulonglong2 a = fw2[i], h = hh2[i];
            f0 = fma2(a.x, h.x, f0);
            f1 = fma2(a.y, h.y, f1);
        }
        float2 ff = upk2(add2(f0, f1));
        float s = ff.x + ff.y;
        s += __shfl_xor_sync(0xAAAAAAAAu, s, 2);
        s += __shfl_xor_sync(0xAAAAAAAAu, s, 4);
        if ((lane & 7) == 1) obase[(size_t)(T_ - 1) * OUT_ + o] = s + sfcb[o];
    }
    if (tid < H_) h_final[(size_t)b * H_ + tid] = hcur[tid];
}

// ============================================================================
extern "C" void kernel_launch(void* const* d_in, const int* in_sizes, int n_in,
                              void* d_out, int out_size) {
    const float* x    = (const float*)d_in[0];
    const float* Wih0 = (const float*)d_in[1];
    const float* Whh0 = (const float*)d_in[2];
    const float* bih0 = (const float*)d_in[3];
    const float* bhh0 = (const float*)d_in[4];
    const float* Wih1 = (const float*)d_in[5];
    const float* Whh1 = (const float*)d_in[6];
    const float* bih1 = (const float*)d_in[7];
    const float* bhh1 = (const float*)d_in[8];
    const float* fcw  = (const float*)d_in[9];
    const float* fcb  = (const float*)d_in[10];

    float* out  = (float*)d_out;                       // [B,T,OUT]
    float* hout = out + (size_t)B_ * T_ * OUT_;        // [2,B,H] stacked after out

    // K1: layer-0 input projection (bulk)
    k1_gi0<<<BT_ / 16, 384>>>(x, Wih0, bih0);
    // K2: layer-0 recurrence -> y0, h[0]
    k_scan<<<B_, 256>>>(Whh0, bhh0, /*store_y=*/1, hout,
                        fcw, fcb, out, /*do_fc=*/0);
    // K3: layer-1 input projection (bulk GEMM over y0)
    k3_gi1<<<dim3(BT_ / 64, G_ / 64), 256>>>(Wih1, bih1);
    // K4: layer-1 recurrence + fused FC head -> out, h[1]
    k_scan<<<B_, 256>>>(Whh1, bhh1, /*store_y=*/0, hout + (size_t)B_ * H_,
                        fcw, fcb, out, /*do_fc=*/1);
}

// round 7
// speedup vs baseline: 1.6537x; 1.6537x over previous
#include <cuda_runtime.h>
#include <cuda_bf16.h>
#include <cstdint>

#define B_   64
#define T_   4096
#define IN_  32
#define H_   128
#define G_   384
#define OUT_ 32
#define BT_  (B_ * T_)
#define GDEPTH 4          // cp.async gi ring depth

// ---------------- scratch (static __device__; allocation-free rule) ----------
__device__ float g_gi[(size_t)BT_ * G_];   // gate pre-activations (reused L0 then L1)
__device__ float g_y0[(size_t)BT_ * H_];   // layer-0 outputs

typedef unsigned long long u64t;

// ---------------- packed f32x2 helpers (sm_103a FFMA2 via PTX) ---------------
__device__ __forceinline__ u64t pk2(float a, float b) {
    u64t r; asm("mov.b64 %0, {%1,%2};" : "=l"(r) : "f"(a), "f"(b)); return r;
}
__device__ __forceinline__ u64t fma2(u64t a, u64t b, u64t c) {
    u64t d; asm("fma.rn.f32x2 %0, %1, %2, %3;" : "=l"(d) : "l"(a), "l"(b), "l"(c)); return d;
}
__device__ __forceinline__ u64t add2(u64t a, u64t b) {
    u64t d; asm("add.rn.f32x2 %0, %1, %2;" : "=l"(d) : "l"(a), "l"(b)); return d;
}
__device__ __forceinline__ float2 upk2(u64t a) {
    float2 f; asm("mov.b64 {%0,%1}, %2;" : "=f"(f.x), "=f"(f.y) : "l"(a)); return f;
}

__device__ __forceinline__ float sigmf(float x) {
    return __fdividef(1.f, 1.f + __expf(-x));
}
__device__ __forceinline__ float tanhfast(float x) {
    float e = __expf(-2.f * x);
    return __fdividef(1.f - e, 1.f + e);
}

__device__ __forceinline__ uint32_t smem_u32(const void* p) {
    uint32_t a;
    asm("{ .reg .u64 t; cvta.to.shared.u64 t, %1; cvt.u32.u64 %0, t; }"
        : "=r"(a) : "l"(p));
    return a;
}
__device__ __forceinline__ void cp_async4(uint32_t saddr, const float* gaddr) {
    asm volatile("cp.async.ca.shared.global [%0], [%1], 4;" :: "r"(saddr), "l"(gaddr));
}
__device__ __forceinline__ void cp_commit() {
    asm volatile("cp.async.commit_group;");
}
__device__ __forceinline__ void cp_wait3() {
    asm volatile("cp.async.wait_group 3;");
}

// ============================================================================
// K1: gi0 = x @ W_ih0^T + b_ih0    (x: [BT,32], W: [384,32]) -> g_gi [BT,384]
// ============================================================================
__global__ void k1_gi0(const float* __restrict__ x,
                       const float* __restrict__ W,
                       const float* __restrict__ b) {
    __shared__ __align__(16) float sx[16 * IN_];
    const int tid = threadIdx.x;                 // gate row 0..383
    const size_t bt0 = (size_t)blockIdx.x * 16;

    for (int i = tid; i < 16 * IN_; i += 384) sx[i] = x[bt0 * IN_ + i];

    u64t wp[16];
    {
        const float4* wr = (const float4*)(W + (size_t)tid * IN_);
#pragma unroll
        for (int q = 0; q < 8; q++) {
            float4 w4 = __ldg(wr + q);
            wp[2 * q]     = pk2(w4.x, w4.y);
            wp[2 * q + 1] = pk2(w4.z, w4.w);
        }
    }
    const float bias = __ldg(b + tid);
    __syncthreads();

#pragma unroll 4
    for (int row = 0; row < 16; row++) {
        const ulonglong2* xr = (const ulonglong2*)(sx + row * IN_);
        u64t a0 = 0ull, a1 = 0ull;
#pragma unroll
        for (int q = 0; q < 8; q++) {
            ulonglong2 xp = xr[q];
            a0 = fma2(wp[2 * q],     xp.x, a0);
            a1 = fma2(wp[2 * q + 1], xp.y, a1);
        }
        float2 s = upk2(add2(a0, a1));
        g_gi[(bt0 + row) * G_ + tid] = s.x + s.y + bias;
    }
}

// ============================================================================
// K3: gi1 = y0 @ W_ih1^T + b_ih1   (y0: [BT,128], W: [384,128]) -> g_gi
// ============================================================================
__global__ void k3_gi1(const float* __restrict__ W,
                       const float* __restrict__ b) {
    __shared__ float sA[16][64];
    __shared__ float sB[16][64];
    const int tid = threadIdx.x;
    const int m0 = blockIdx.x * 64;   // bt rows
    const int n0 = blockIdx.y * 64;   // gate rows
    const int tx = tid & 15, ty = tid >> 4;
    const int lrow = tid >> 2, lk = (tid & 3) * 4;

    u64t acc2[4][2] = {};
    for (int k0 = 0; k0 < H_; k0 += 16) {
        float4 a4 = *(const float4*)(g_y0 + (size_t)(m0 + lrow) * H_ + k0 + lk);
        float4 b4 = __ldg((const float4*)(W + (size_t)(n0 + lrow) * H_ + k0 + lk));
        sA[lk + 0][lrow] = a4.x; sA[lk + 1][lrow] = a4.y;
        sA[lk + 2][lrow] = a4.z; sA[lk + 3][lrow] = a4.w;
        sB[lk + 0][lrow] = b4.x; sB[lk + 1][lrow] = b4.y;
        sB[lk + 2][lrow] = b4.z; sB[lk + 3][lrow] = b4.w;
        __syncthreads();
#pragma unroll
        for (int kk = 0; kk < 16; kk++) {
            float4 av = *(const float4*)(&sA[kk][ty * 4]);
            float4 bv = *(const float4*)(&sB[kk][tx * 4]);
            u64t b01 = pk2(bv.x, bv.y), b23 = pk2(bv.z, bv.w);
            float aa[4] = {av.x, av.y, av.z, av.w};
#pragma unroll
            for (int i = 0; i < 4; i++) {
                u64t ai = pk2(aa[i], aa[i]);
                acc2[i][0] = fma2(ai, b01, acc2[i][0]);
                acc2[i][1] = fma2(ai, b23, acc2[i][1]);
            }
        }
        __syncthreads();
    }
    float4 bv = __ldg((const float4*)(b + n0 + tx * 4));
#pragma unroll
    for (int i = 0; i < 4; i++) {
        float2 p01 = upk2(acc2[i][0]), p23 = upk2(acc2[i][1]);
        float4 o;
        o.x = p01.x + bv.x; o.y = p01.y + bv.y;
        o.z = p23.x + bv.z; o.w = p23.y + bv.w;
        *(float4*)(g_gi + (size_t)(m0 + ty * 4 + i) * G_ + n0 + tx * 4) = o;
    }
}

// ============================================================================
// K2/K4: GRU recurrence. 64 CTAs (one per batch), 384 threads (one per gate
// row). W_hh row register-resident as 64 packed f32x2. h double-buffered in
// SMEM (2 barriers/step). n-threads fuse the h-update; r/z threads compute
// the FC head for step t-1 during that phase.
// gi fed through a 4-deep cp.async SMEM ring (register-free DRAM prefetch).
// ============================================================================
__global__ void __launch_bounds__(384, 1) k_scan(
    const float* __restrict__ Whh, const float* __restrict__ bhh,
    const int store_y, float* __restrict__ h_final,
    const float* __restrict__ fcw, const float* __restrict__ fcb,
    float* __restrict__ out, const int do_fc)
{
    __shared__ __align__(16) float sh_h0[H_];
    __shared__ __align__(16) float sh_h1[H_];
    __shared__ float sh_r[H_], sh_z[H_];
    __shared__ __align__(16) float sfc[OUT_ * H_];
    __shared__ float sfcb[OUT_];
    __shared__ __align__(16) float sgi[GDEPTH][G_];   // gi prefetch ring

    const int r = threadIdx.x;       // gate row (r:0-127, z:128-255, n:256-383)
    const int b = blockIdx.x;        // batch

    u64t wp[64];
    {
        const float4* wr = (const float4*)(Whh + (size_t)r * H_);
#pragma unroll
        for (int q = 0; q < 16; q++) {
            float4 wA = __ldg(wr + 2 * q);
            float4 wB = __ldg(wr + 2 * q + 1);
            wp[4 * q + 0] = pk2(wA.x, wA.y);
            wp[4 * q + 1] = pk2(wA.z, wA.w);
            wp[4 * q + 2] = pk2(wB.x, wB.y);
            wp[4 * q + 3] = pk2(wB.z, wB.w);
        }
    }
    const float bias = __ldg(bhh + r);
    if (r < H_) sh_h0[r] = 0.f;
    if (do_fc) {
        for (int i = r; i < OUT_ * H_; i += 384) sfc[i] = fcw[i];
        if (r < OUT_) sfcb[r] = fcb[r];
    }

    // ---- gi ring prologue: fill GDEPTH stages -------------------------------
    const float* gip = g_gi + (size_t)b * T_ * G_ + r;
    const uint32_t sgi_base = smem_u32(&sgi[0][r]);
#pragma unroll
    for (int d = 0; d < GDEPTH; d++) {
        cp_async4(sgi_base + (uint32_t)d * (G_ * 4), gip + (size_t)d * G_);
        cp_commit();
    }
    __syncthreads();

    float* hcur = sh_h0;
    float* hnxt = sh_h1;
    float* ybase = g_y0 + (size_t)b * T_ * H_ + (r - 256);     // n-threads only
    float* obase = out + (size_t)b * T_ * OUT_;

    const int o   = r >> 3;          // FC output index (r/z threads)
    const int seg = r & 7;
    const float* fcrow = sfc + o * H_ + seg * 16;

    for (int t = 0; t < T_; t++) {
        const int slot = t & (GDEPTH - 1);

        cp_wait3();                                            // stage t landed
        const float gi_cur = sgi[slot][r];

        // refill this slot for step t+GDEPTH (clamped; redundant load at tail)
        const int tp = (t + GDEPTH < T_) ? t + GDEPTH : T_ - 1;
        cp_async4(sgi_base + (uint32_t)slot * (G_ * 4), gip + (size_t)tp * G_);
        cp_commit();

        // ---- phase 1: gh = W_hh[r,:] . h + b ; r,z publish sigmoids --------
        u64t a0 = 0ull, a1 = 0ull, a2 = 0ull, a3 = 0ull;
        const ulonglong2* h2 = (const ulonglong2*)hcur;
#pragma unroll
        for (int q = 0; q < 16; q++) {
            ulonglong2 p0 = h2[2 * q];
            ulonglong2 p1 = h2[2 * q + 1];
            a0 = fma2(wp[4 * q + 0], p0.x, a0);
            a1 = fma2(wp[4 * q + 1], p0.y, a1);
            a2 = fma2(wp[4 * q + 2], p1.x, a2);
            a3 = fma2(wp[4 * q + 3], p1.y, a3);
        }
        float2 sf = upk2(add2(add2(a0, a1), add2(a2, a3)));
        const float gh = sf.x + sf.y + bias;

        if (r < 128)      sh_r[r]       = sigmf(gi_cur + gh);
        else if (r < 256) sh_z[r - 128] = sigmf(gi_cur + gh);
        __syncthreads();                                        // bar 1

        // ---- phase 2: n-threads update h; r/z threads do FC for t-1 --------
        if (r >= 256) {
            const int j = r - 256;
            const float nv = tanhfast(fmaf(sh_r[j], gh, gi_cur));
            const float hold = hcur[j];
            const float hnew = fmaf(sh_z[j], hold - nv, nv);    // (1-z)*n + z*h
            hnxt[j] = hnew;
            if (store_y) ybase[(size_t)t * H_] = hnew;
        } else if (do_fc && t > 0) {
            const float* hh = hcur + seg * 16;                  // h_{t-1}
            float s = 0.f;
#pragma unroll
            for (int k = 0; k < 16; k++) s = fmaf(fcrow[k], hh[k], s);
            s += __shfl_down_sync(0xffffffffu, s, 4, 8);
            s += __shfl_down_sync(0xffffffffu, s, 2, 8);
            s += __shfl_down_sync(0xffffffffu, s, 1, 8);
            if (seg == 0) obase[(size_t)(t - 1) * OUT_ + o] = s + sfcb[o];
        }
        __syncthreads();                                        // bar 2

        float* tmp = hcur; hcur = hnxt; hnxt = tmp;
    }

    // final-step FC (h_{T-1} sits in hcur after the last swap)
    if (do_fc && r < 256) {
        const float* hh = hcur + seg * 16;
        float s = 0.f;
#pragma unroll
        for (int k = 0; k < 16; k++) s = fmaf(fcrow[k], hh[k], s);
        s += __shfl_down_sync(0xffffffffu, s, 4, 8);
        s += __shfl_down_sync(0xffffffffu, s, 2, 8);
        s += __shfl_down_sync(0xffffffffu, s, 1, 8);
        if (seg == 0) obase[(size_t)(T_ - 1) * OUT_ + o] = s + sfcb[o];
    }
    if (r < H_) h_final[(size_t)b * H_ + r] = hcur[r];
}

// ============================================================================
extern "C" void kernel_launch(void* const* d_in, const int* in_sizes, int n_in,
                              void* d_out, int out_size) {
    const float* x    = (const float*)d_in[0];
    const float* Wih0 = (const float*)d_in[1];
    const float* Whh0 = (const float*)d_in[2];
    const float* bih0 = (const float*)d_in[3];
    const float* bhh0 = (const float*)d_in[4];
    const float* Wih1 = (const float*)d_in[5];
    const float* Whh1 = (const float*)d_in[6];
    const float* bih1 = (const float*)d_in[7];
    const float* bhh1 = (const float*)d_in[8];
    const float* fcw  = (const float*)d_in[9];
    const float* fcb  = (const float*)d_in[10];

    float* out  = (float*)d_out;                       // [B,T,OUT]
    float* hout = out + (size_t)B_ * T_ * OUT_;        // [2,B,H] stacked after out

    // K1: layer-0 input projection (bulk)
    k1_gi0<<<BT_ / 16, 384>>>(x, Wih0, bih0);
    // K2: layer-0 recurrence -> y0, h[0]
    k_scan<<<B_, 384>>>(Whh0, bhh0, /*store_y=*/1, hout,
                        fcw, fcb, out, /*do_fc=*/0);
    // K3: layer-1 input projection (bulk GEMM over y0)
    k3_gi1<<<dim3(BT_ / 64, G_ / 64), 256>>>(Wih1, bih1);
    // K4: layer-1 recurrence + fused FC head -> out, h[1]
    k_scan<<<B_, 384>>>(Whh1, bhh1, /*store_y=*/0, hout + (size_t)B_ * H_,
                        fcw, fcb, out, /*do_fc=*/1);
}